// round 2
// baseline (speedup 1.0000x reference)
#include <cuda_runtime.h>
#include <mma.h>
using namespace nvcuda;

#define DOUT 1024
#define NROWS 8192
#define NCAP 10

// ---------------- scratch (device globals: allocation-rule-safe) ----------
__device__ float g_cos[NCAP * 512];
__device__ float g_sin[NCAP * 512];
__device__ float g_Ux[(size_t)NROWS * 3072];
__device__ float g_SR[(size_t)NROWS * 1024];
__device__ float g_SG[(size_t)NROWS * 1024];

// ---------------- trig table ----------------------------------------------
__global__ void trig_kernel(const float* __restrict__ theta) {
    int i = blockIdx.x;
    int a = threadIdx.x;
    float s, c;
    sincosf(theta[i * 512 + a], &s, &c);
    g_cos[i * 512 + a] = c;
    g_sin[i * 512 + a] = s;
}

// ---------------- tf32 WMMA GEMM: C = A(MxK) * B(KxN), all row-major ------
constexpr int BM = 128, BN = 128, BK = 16;

__global__ __launch_bounds__(256) void gemm_tf32(
    const float* __restrict__ A, const float* __restrict__ Bm,
    float* __restrict__ C, int M, int N, int K)
{
    __shared__ float As[BM * BK];   // [128][16]
    __shared__ float Bs[BK * BN];   // [16][128]

    const int tid  = threadIdx.x;
    const int warp = tid >> 5;
    const int wm   = warp >> 2;   // 2 warps along M (64 rows each)
    const int wn   = warp & 3;    // 4 warps along N (32 cols each)
    const int bx   = blockIdx.x;
    const int by   = blockIdx.y;

    wmma::fragment<wmma::accumulator, 16, 16, 8, float> acc[4][2];
#pragma unroll
    for (int i = 0; i < 4; i++)
#pragma unroll
        for (int j = 0; j < 2; j++) wmma::fill_fragment(acc[i][j], 0.0f);

    const float* Ab = A + (size_t)(by * BM) * K;

    for (int k0 = 0; k0 < K; k0 += BK) {
        // A tile: 128x16 floats = 512 float4
#pragma unroll
        for (int it = 0; it < 2; it++) {
            int idx = tid + it * 256;
            int r = idx >> 2, c4 = idx & 3;
            reinterpret_cast<float4*>(As)[idx] =
                *reinterpret_cast<const float4*>(Ab + (size_t)r * K + k0 + c4 * 4);
        }
        // B tile: 16x128 floats = 512 float4
#pragma unroll
        for (int it = 0; it < 2; it++) {
            int idx = tid + it * 256;
            int r = idx >> 5, c4 = idx & 31;
            reinterpret_cast<float4*>(Bs)[idx] =
                *reinterpret_cast<const float4*>(Bm + (size_t)(k0 + r) * N + bx * BN + c4 * 4);
        }
        __syncthreads();

#pragma unroll
        for (int kk = 0; kk < BK; kk += 8) {
            wmma::fragment<wmma::matrix_a, 16, 16, 8, wmma::precision::tf32, wmma::row_major> af[4];
            wmma::fragment<wmma::matrix_b, 16, 16, 8, wmma::precision::tf32, wmma::row_major> bf[2];
#pragma unroll
            for (int mi = 0; mi < 4; mi++) {
                wmma::load_matrix_sync(af[mi], As + (wm * 64 + mi * 16) * BK + kk, BK);
#pragma unroll
                for (int t = 0; t < af[mi].num_elements; t++)
                    af[mi].x[t] = wmma::__float_to_tf32(af[mi].x[t]);
            }
#pragma unroll
            for (int ni = 0; ni < 2; ni++) {
                wmma::load_matrix_sync(bf[ni], Bs + kk * BN + wn * 32 + ni * 16, BN);
#pragma unroll
                for (int t = 0; t < bf[ni].num_elements; t++)
                    bf[ni].x[t] = wmma::__float_to_tf32(bf[ni].x[t]);
            }
#pragma unroll
            for (int mi = 0; mi < 4; mi++)
#pragma unroll
                for (int ni = 0; ni < 2; ni++)
                    wmma::mma_sync(acc[mi][ni], af[mi], bf[ni], acc[mi][ni]);
        }
        __syncthreads();
    }

#pragma unroll
    for (int mi = 0; mi < 4; mi++)
#pragma unroll
        for (int ni = 0; ni < 2; ni++)
            wmma::store_matrix_sync(
                C + (size_t)(by * BM + wm * 64 + mi * 16) * N + bx * BN + wn * 32 + ni * 16,
                acc[mi][ni], N, wmma::mem_row_major);
}

// ---------------- fused butterfly + gates + modReLU -----------------------
// IND_EXE[i][m] == m ^ (1 << (9-i)); angle index for lower partner:
//   q = m mod 2^(10-i), b = m >> (10-i), a = q*2^i + b  (a < 512)
// Givens rotation: h[m] <- c*h[m] - s*h[m'], h[m'] <- s*h[m] + c*h[m']
__global__ __launch_bounds__(256) void fuse_kernel(
    const float* __restrict__ state,
    const float* __restrict__ br, const float* __restrict__ bg,
    const float* __restrict__ bc, float* __restrict__ out)
{
    __shared__ float h[DOUT];
    const int row = blockIdx.x;
    const int t   = threadIdx.x;
    const float* st = state + (size_t)row * DOUT;

    for (int j = t; j < DOUT; j += 256) h[j] = st[j];
    __syncthreads();

#pragma unroll
    for (int i = 0; i < NCAP; i++) {
        const int hb = 9 - i;          // bit that distinguishes the pair
        const int stride = 1 << hb;
#pragma unroll
        for (int pp = 0; pp < 2; pp++) {
            int p = t + pp * 256;                       // pair id 0..511
            int m = ((p >> hb) << (hb + 1)) | (p & (stride - 1)); // lower partner
            int q = m & ((1 << (10 - i)) - 1);
            int b = m >> (10 - i);
            int a = (q << i) + b;                       // < 512
            float c = g_cos[i * 512 + a];
            float s = g_sin[i * 512 + a];
            float h0 = h[m], h1 = h[m + stride];
            h[m]          = c * h0 - s * h1;
            h[m + stride] = s * h0 + c * h1;
        }
        __syncthreads();
    }

    const float* uxr = g_Ux + (size_t)row * 3072;
    const float* srr = g_SR + (size_t)row * DOUT;
    const float* sgr = g_SG + (size_t)row * DOUT;

    for (int j = t; j < DOUT; j += 256) {
        float ucx = uxr[j];
        float rv = 1.0f / (1.0f + expf(-(uxr[1024 + j] + srr[j] + br[j])));
        float gv = 1.0f / (1.0f + expf(-(uxr[2048 + j] + sgr[j] + bg[j])));
        float pre = rv * h[j] + ucx;
        float mag = fabsf(pre) + 0.001f + bc[j];
        float sgn = (pre > 0.0f) ? 1.0f : ((pre < 0.0f) ? -1.0f : 0.0f);
        float cv  = sgn * fmaxf(mag, 0.0f);
        out[(size_t)row * DOUT + j] = gv * st[j] + (1.0f - gv) * cv;
    }
}

// ---------------- launch ---------------------------------------------------
extern "C" void kernel_launch(void* const* d_in, const int* in_sizes, int n_in,
                              void* d_out, int out_size)
{
    const float* x     = (const float*)d_in[0];
    const float* state = (const float*)d_in[1];
    const float* theta = (const float*)d_in[2];
    const float* U     = (const float*)d_in[3];
    const float* W_r   = (const float*)d_in[4];
    const float* W_g   = (const float*)d_in[5];
    const float* br    = (const float*)d_in[6];
    const float* bg    = (const float*)d_in[7];
    const float* bc    = (const float*)d_in[8];
    float* out = (float*)d_out;

    float *ux, *sr, *sg;
    cudaGetSymbolAddress((void**)&ux, g_Ux);
    cudaGetSymbolAddress((void**)&sr, g_SR);
    cudaGetSymbolAddress((void**)&sg, g_SG);

    trig_kernel<<<NCAP, 512>>>(theta);
    gemm_tf32<<<dim3(3072 / BN, NROWS / BM), 256>>>(x,     U,   ux, NROWS, 3072, 1024);
    gemm_tf32<<<dim3(1024 / BN, NROWS / BM), 256>>>(state, W_r, sr, NROWS, 1024, 1024);
    gemm_tf32<<<dim3(1024 / BN, NROWS / BM), 256>>>(state, W_g, sg, NROWS, 1024, 1024);
    fuse_kernel<<<NROWS, 256>>>(state, br, bg, bc, out);
}

// round 5
// speedup vs baseline: 2.4836x; 2.4836x over previous
#include <cuda_runtime.h>
#include <cstdint>

#define DOUT 1024
#define NROWS 8192
#define NCAP 10
#define KDIM 1024

// ---------------- scratch (device globals: allocation-rule-safe) ----------
__device__ float g_cos[NCAP * 512];
__device__ float g_sin[NCAP * 512];
__device__ float g_Ux[(size_t)NROWS * 3072];
__device__ float g_SR[(size_t)NROWS * 1024];
__device__ float g_SG[(size_t)NROWS * 1024];

// ---------------- helpers ---------------------------------------------------
__device__ __forceinline__ uint32_t smem_u32(const void* p) {
    uint32_t a;
    asm("{ .reg .u64 t; cvta.to.shared.u64 t, %1; cvt.u32.u64 %0, t; }" : "=r"(a) : "l"(p));
    return a;
}
__device__ __forceinline__ void cp16(uint32_t s, const void* g) {
    asm volatile("cp.async.cg.shared.global [%0], [%1], 16;" :: "r"(s), "l"(g));
}
#define CP_COMMIT() asm volatile("cp.async.commit_group;" ::: "memory")
#define CP_WAIT(n)  asm volatile("cp.async.wait_group %0;" :: "n"(n) : "memory")

__device__ __forceinline__ void mma_tf32(float* d, const uint32_t* a, const uint32_t* b) {
    asm volatile(
        "mma.sync.aligned.m16n8k8.row.col.f32.tf32.tf32.f32 "
        "{%0,%1,%2,%3}, {%4,%5,%6,%7}, {%8,%9}, {%0,%1,%2,%3};"
        : "+f"(d[0]), "+f"(d[1]), "+f"(d[2]), "+f"(d[3])
        : "r"(a[0]), "r"(a[1]), "r"(a[2]), "r"(a[3]), "r"(b[0]), "r"(b[1]));
}

// ---------------- trig table ----------------------------------------------
__global__ void trig_kernel(const float* __restrict__ theta) {
    int i = blockIdx.x, a = threadIdx.x;
    float s, c;
    sincosf(theta[i * 512 + a], &s, &c);
    g_cos[i * 512 + a] = c;
    g_sin[i * 512 + a] = s;
}

// ---------------- mma.sync tf32 GEMM ---------------------------------------
// C[M,N] = A[M,K] * B[K,N], A,B,C row-major. BM=128, BN=256, BK=32.
// 512 threads = 16 warps (4 along M x 4 along N), warp tile 32x64.
constexpr int BM = 128, BN = 256, BK = 32, S = 3;
constexpr int NSTAGE = KDIM / BK;          // 32
constexpr int A_STRIDE = 36;               // floats per A row (pad: bank = 4r+k)
constexpr int B_STRIDE = 264;              // floats per B row (pad: bank = 8k+n)
constexpr int A_FLOATS = BM * A_STRIDE;    // 4608
constexpr int B_FLOATS = BK * B_STRIDE;    // 8448
constexpr int SMEM_FLOATS = S * (A_FLOATS + B_FLOATS);   // 39168
constexpr int SMEM_SZ = SMEM_FLOATS * 4;                 // 156672 B

__global__ __launch_bounds__(512, 1) void gemm_mma(const float* __restrict__ x,
                                                   const float* __restrict__ U,
                                                   const float* __restrict__ Wr,
                                                   const float* __restrict__ Wg,
                                                   const float* __restrict__ state) {
    extern __shared__ __align__(1024) float smem[];
    float* As = smem;                       // S stages of A
    float* Bs = smem + S * A_FLOATS;        // S stages of B
    const uint32_t sb = smem_u32(smem);
    const uint32_t sbB = sb + S * A_FLOATS * 4;

    const int tid  = threadIdx.x;
    const int lane = tid & 31;
    const int wid  = tid >> 5;
    const int wm   = wid >> 2;   // 0..3 (32 rows each)
    const int wn   = wid & 3;    // 0..3 (64 cols each)

    // ---- tile mapping: 768 U-tiles, then 256 Wr, 256 Wg ----
    const float* A; const float* B; float* C; int ldn, m0, n0;
    int bid = blockIdx.x;
    if (bid < 768) {
        A = x; B = U; C = g_Ux; ldn = 3072;
        m0 = (bid & 63) * BM; n0 = (bid >> 6) * BN;
    } else {
        int t = bid - 768, g = t >> 8, tt = t & 255;
        A = state; B = g ? Wg : Wr; C = g ? g_SG : g_SR; ldn = 1024;
        m0 = (tt & 63) * BM; n0 = (tt >> 6) * BN;
    }

    // ---- stage loader: A 1024 chunks, B 2048 chunks of 16B ----
    auto load_stage = [&](int st) {
        const int buf = st % S;
        const float* Ag = A + (size_t)m0 * KDIM + st * BK;
        const uint32_t ab = sb + (uint32_t)(buf * A_FLOATS * 4);
#pragma unroll
        for (int i = 0; i < 2; i++) {
            int idx = tid + i * 512;
            int r = idx >> 3, c = idx & 7;                 // 8 chunks per 32-float row
            cp16(ab + (uint32_t)((r * A_STRIDE + c * 4) * 4),
                 Ag + (size_t)r * KDIM + c * 4);
        }
        const float* Bg = B + (size_t)st * BK * ldn + n0;
        const uint32_t bb = sbB + (uint32_t)(buf * B_FLOATS * 4);
#pragma unroll
        for (int i = 0; i < 4; i++) {
            int idx = tid + i * 512;
            int k = idx >> 6, c = idx & 63;                // 64 chunks per 256-float row
            cp16(bb + (uint32_t)((k * B_STRIDE + c * 4) * 4),
                 Bg + (size_t)k * ldn + c * 4);
        }
        CP_COMMIT();
    };

    load_stage(0);
    load_stage(1);

    float acc[2][8][4];
#pragma unroll
    for (int mt = 0; mt < 2; mt++)
#pragma unroll
        for (int nt = 0; nt < 8; nt++)
#pragma unroll
            for (int j = 0; j < 4; j++) acc[mt][nt][j] = 0.0f;

    const int ar = lane >> 2;      // 0..7
    const int ak = lane & 3;       // 0..3
    const int bn = lane >> 2;      // 0..7

    for (int ks = 0; ks < NSTAGE; ks++) {
        if (ks < NSTAGE - 1) CP_WAIT(1); else CP_WAIT(0);
        __syncthreads();
        if (ks + 2 < NSTAGE) load_stage(ks + 2);

        const float* Ab = As + (ks % S) * A_FLOATS + (wm * 32 + ar) * A_STRIDE + ak;
        const float* Bb = Bs + (ks % S) * B_FLOATS + ak * B_STRIDE + wn * 64 + bn;

#pragma unroll
        for (int kk = 0; kk < BK; kk += 8) {
            uint32_t afr[2][4];
#pragma unroll
            for (int mt = 0; mt < 2; mt++) {
                const float* ap = Ab + mt * 16 * A_STRIDE + kk;
                afr[mt][0] = __float_as_uint(ap[0]);
                afr[mt][1] = __float_as_uint(ap[8 * A_STRIDE]);
                afr[mt][2] = __float_as_uint(ap[4]);
                afr[mt][3] = __float_as_uint(ap[8 * A_STRIDE + 4]);
            }
            uint32_t bfr[8][2];
#pragma unroll
            for (int nt = 0; nt < 8; nt++) {
                const float* bp = Bb + kk * B_STRIDE + nt * 8;
                bfr[nt][0] = __float_as_uint(bp[0]);
                bfr[nt][1] = __float_as_uint(bp[4 * B_STRIDE]);
            }
#pragma unroll
            for (int mt = 0; mt < 2; mt++)
#pragma unroll
                for (int nt = 0; nt < 8; nt++)
                    mma_tf32(acc[mt][nt], afr[mt], bfr[nt]);
        }
        __syncthreads();
    }

    // ---- epilogue: direct v2 stores ----
    const int crow = m0 + wm * 32 + (lane >> 2);
    const int ccol = n0 + wn * 64 + (lane & 3) * 2;
#pragma unroll
    for (int mt = 0; mt < 2; mt++)
#pragma unroll
        for (int nt = 0; nt < 8; nt++) {
            float* p0 = C + (size_t)(crow + mt * 16) * ldn + ccol + nt * 8;
            float* p1 = p0 + 8 * ldn;
            *reinterpret_cast<float2*>(p0) = make_float2(acc[mt][nt][0], acc[mt][nt][1]);
            *reinterpret_cast<float2*>(p1) = make_float2(acc[mt][nt][2], acc[mt][nt][3]);
        }
}

// ---------------- fused butterfly + gates + modReLU -----------------------
__global__ __launch_bounds__(256) void fuse_kernel(
    const float* __restrict__ state,
    const float* __restrict__ br, const float* __restrict__ bg,
    const float* __restrict__ bc, float* __restrict__ out)
{
    __shared__ float h[DOUT];
    const int row = blockIdx.x;
    const int t = threadIdx.x;
    const float* st = state + (size_t)row * DOUT;

    for (int j = t; j < DOUT; j += 256) h[j] = st[j];
    __syncthreads();

#pragma unroll
    for (int i = 0; i < NCAP; i++) {
        const int hb = 9 - i;
        const int stride = 1 << hb;
#pragma unroll
        for (int pp = 0; pp < 2; pp++) {
            int p = t + pp * 256;
            int m = ((p >> hb) << (hb + 1)) | (p & (stride - 1));
            int q = m & ((1 << (10 - i)) - 1);
            int b = m >> (10 - i);
            int a = (q << i) + b;
            float c = g_cos[i * 512 + a];
            float s = g_sin[i * 512 + a];
            float h0 = h[m], h1 = h[m + stride];
            h[m]          = c * h0 - s * h1;
            h[m + stride] = s * h0 + c * h1;
        }
        __syncthreads();
    }

    const float* uxr = g_Ux + (size_t)row * 3072;
    const float* srr = g_SR + (size_t)row * DOUT;
    const float* sgr = g_SG + (size_t)row * DOUT;

    for (int j = t; j < DOUT; j += 256) {
        float ucx = uxr[j];
        float rv = 1.0f / (1.0f + expf(-(uxr[1024 + j] + srr[j] + br[j])));
        float gv = 1.0f / (1.0f + expf(-(uxr[2048 + j] + sgr[j] + bg[j])));
        float pre = rv * h[j] + ucx;
        float mag = fabsf(pre) + 0.001f + bc[j];
        float sgn = (pre > 0.0f) ? 1.0f : ((pre < 0.0f) ? -1.0f : 0.0f);
        float cv = sgn * fmaxf(mag, 0.0f);
        out[(size_t)row * DOUT + j] = gv * st[j] + (1.0f - gv) * cv;
    }
}

// ---------------- launch ---------------------------------------------------
extern "C" void kernel_launch(void* const* d_in, const int* in_sizes, int n_in,
                              void* d_out, int out_size)
{
    const float* x     = (const float*)d_in[0];
    const float* state = (const float*)d_in[1];
    const float* theta = (const float*)d_in[2];
    const float* U     = (const float*)d_in[3];
    const float* W_r   = (const float*)d_in[4];
    const float* W_g   = (const float*)d_in[5];
    const float* br    = (const float*)d_in[6];
    const float* bg    = (const float*)d_in[7];
    const float* bc    = (const float*)d_in[8];
    float* out = (float*)d_out;

    static bool attr_done = false;
    if (!attr_done) {
        cudaFuncSetAttribute(gemm_mma, cudaFuncAttributeMaxDynamicSharedMemorySize, SMEM_SZ);
        attr_done = true;
    }

    trig_kernel<<<NCAP, 512>>>(theta);
    gemm_mma<<<1280, 512, SMEM_SZ>>>(x, U, W_r, W_g, state);
    fuse_kernel<<<NROWS, 256>>>(state, br, bg, bc, out);
}

// round 7
// speedup vs baseline: 3.5731x; 1.4387x over previous
#include <cuda_runtime.h>
#include <cuda_fp16.h>
#include <cstdint>

#define DOUT 1024
#define NROWS 8192
#define NCAP 10
#define KDIM 1024

// ---------------- scratch (device globals: allocation-rule-safe) ----------
__device__ float g_cos[NCAP * 512];
__device__ float g_sin[NCAP * 512];
__device__ float g_Ux[(size_t)NROWS * 3072];
__device__ float g_SR[(size_t)NROWS * 1024];
__device__ float g_SG[(size_t)NROWS * 1024];
__device__ __half g_xh[(size_t)NROWS * 1024];
__device__ __half g_sh[(size_t)NROWS * 1024];
__device__ __half g_Uh[(size_t)1024 * 3072];
__device__ __half g_Wrh[(size_t)1024 * 1024];
__device__ __half g_Wgh[(size_t)1024 * 1024];

// ---------------- helpers ---------------------------------------------------
__device__ __forceinline__ uint32_t smem_u32(const void* p) {
    uint32_t a;
    asm("{ .reg .u64 t; cvta.to.shared.u64 t, %1; cvt.u32.u64 %0, t; }" : "=r"(a) : "l"(p));
    return a;
}
__device__ __forceinline__ void cp16(uint32_t s, const void* g) {
    asm volatile("cp.async.cg.shared.global [%0], [%1], 16;" :: "r"(s), "l"(g));
}
#define CP_COMMIT() asm volatile("cp.async.commit_group;" ::: "memory")
#define CP_WAIT(n)  asm volatile("cp.async.wait_group %0;" :: "n"(n) : "memory")

__device__ __forceinline__ void ldsm_x4(uint32_t* r, uint32_t addr) {
    asm volatile("ldmatrix.sync.aligned.m8n8.x4.shared.b16 {%0,%1,%2,%3}, [%4];"
                 : "=r"(r[0]), "=r"(r[1]), "=r"(r[2]), "=r"(r[3]) : "r"(addr));
}
__device__ __forceinline__ void ldsm_x4_t(uint32_t* r, uint32_t addr) {
    asm volatile("ldmatrix.sync.aligned.m8n8.x4.trans.shared.b16 {%0,%1,%2,%3}, [%4];"
                 : "=r"(r[0]), "=r"(r[1]), "=r"(r[2]), "=r"(r[3]) : "r"(addr));
}
__device__ __forceinline__ void mma_f16(float* d, const uint32_t* a, const uint32_t* b) {
    asm volatile(
        "mma.sync.aligned.m16n8k16.row.col.f32.f16.f16.f32 "
        "{%0,%1,%2,%3}, {%4,%5,%6,%7}, {%8,%9}, {%0,%1,%2,%3};"
        : "+f"(d[0]), "+f"(d[1]), "+f"(d[2]), "+f"(d[3])
        : "r"(a[0]), "r"(a[1]), "r"(a[2]), "r"(a[3]), "r"(b[0]), "r"(b[1]));
}

// ---------------- trig table ----------------------------------------------
__global__ void trig_kernel(const float* __restrict__ theta) {
    int i = blockIdx.x, a = threadIdx.x;
    float s, c;
    sincosf(theta[i * 512 + a], &s, &c);
    g_cos[i * 512 + a] = c;
    g_sin[i * 512 + a] = s;
}

// ---------------- fp32 -> fp16 convert -------------------------------------
__global__ __launch_bounds__(256) void f2h_kernel(const float* __restrict__ in,
                                                  __half* __restrict__ out, int n4) {
    int i = blockIdx.x * 256 + threadIdx.x;
    int stride = gridDim.x * 256;
    for (; i < n4; i += stride) {
        float4 v = reinterpret_cast<const float4*>(in)[i];
        __half2 h0 = __floats2half2_rn(v.x, v.y);
        __half2 h1 = __floats2half2_rn(v.z, v.w);
        uint2 u;
        u.x = *reinterpret_cast<const uint32_t*>(&h0);
        u.y = *reinterpret_cast<const uint32_t*>(&h1);
        reinterpret_cast<uint2*>(out)[i] = u;
    }
}

// ---------------- mma.sync fp16 GEMM ---------------------------------------
// C[M,N] = A[M,K] * B[K,N] (fp16 in, fp32 acc). BM=128, BN=256, BK=32.
// 512 threads = 16 warps (4 along M x 4 along N), warp tile 32x64.
constexpr int BM = 128, BN = 256, BK = 32, S = 4;
constexpr int NSTAGE = KDIM / BK;            // 32
constexpr int A_LDH = 40;                    // halves per A row (80B: banks 20t mod 32)
constexpr int B_LDH = 264;                   // halves per B row (528B: banks 4t mod 32)
constexpr int A_HALF = BM * A_LDH;           // 5120 halves  (10240 B)
constexpr int B_HALF = BK * B_LDH;           // 8448 halves  (16896 B)
constexpr int A_BYTES = A_HALF * 2;
constexpr int B_BYTES = B_HALF * 2;
constexpr int B_BASE = S * A_BYTES;          // 40960
constexpr int SMEM_SZ = B_BASE + S * B_BYTES; // 108544 B

__global__ __launch_bounds__(512, 1) void gemm_mma(const __half* __restrict__ xh,
                                                   const __half* __restrict__ sh) {
    extern __shared__ __align__(1024) char smem[];
    const uint32_t sb = smem_u32(smem);
    const uint32_t sbB = sb + B_BASE;

    const int tid  = threadIdx.x;
    const int lane = tid & 31;
    const int wid  = tid >> 5;
    const int wm   = wid >> 2;   // 0..3 (32 rows each)
    const int wn   = wid & 3;    // 0..3 (64 cols each)

    // ---- tile mapping: 768 U-tiles, then 256 Wr, 256 Wg ----
    const __half* A; const __half* B; float* C; int ldn, m0, n0;
    int bid = blockIdx.x;
    if (bid < 768) {
        A = xh; B = g_Uh; C = g_Ux; ldn = 3072;
        m0 = (bid & 63) * BM; n0 = (bid >> 6) * BN;
    } else {
        int t = bid - 768, g = t >> 8, tt = t & 255;
        A = sh; B = g ? g_Wgh : g_Wrh; C = g ? g_SG : g_SR; ldn = 1024;
        m0 = (tt & 63) * BM; n0 = (tt >> 6) * BN;
    }

    // ---- stage loader ----
    auto load_stage = [&](int st) {
        const int buf = st & (S - 1);
        const __half* Ag = A + (size_t)m0 * KDIM + st * BK;
        const uint32_t ab = sb + (uint32_t)(buf * A_BYTES);
        {   // A: 128 rows x 32 halves = 512 chunks of 16B, one per thread
            int r = tid >> 2, c = tid & 3;
            cp16(ab + (uint32_t)(r * (A_LDH * 2) + c * 16),
                 Ag + (size_t)r * KDIM + c * 8);
        }
        const __half* Bg = B + (size_t)st * BK * ldn + n0;
        const uint32_t bb = sbB + (uint32_t)(buf * B_BYTES);
#pragma unroll
        for (int i = 0; i < 2; i++) {   // B: 32 rows x 256 halves = 1024 chunks
            int idx = tid + i * 512;
            int k = idx >> 5, c = idx & 31;
            cp16(bb + (uint32_t)(k * (B_LDH * 2) + c * 16),
                 Bg + (size_t)k * ldn + c * 8);
        }
        CP_COMMIT();
    };

    load_stage(0);
    load_stage(1);
    load_stage(2);

    float acc[2][8][4];
#pragma unroll
    for (int mt = 0; mt < 2; mt++)
#pragma unroll
        for (int nt = 0; nt < 8; nt++)
#pragma unroll
            for (int j = 0; j < 4; j++) acc[mt][nt][j] = 0.0f;

    const int lr = lane & 15;      // ldmatrix row provider
    const int lc = lane >> 4;      // ldmatrix col-chunk provider

    for (int ks = 0; ks < NSTAGE; ks++) {
        CP_WAIT(2);
        __syncthreads();
        if (ks + 3 < NSTAGE) load_stage(ks + 3); else CP_COMMIT();

        const int buf = ks & (S - 1);
        // A base (bytes): row = wm*32 + lr (+ mt*16), col-halves = lc*8 + kk
        const uint32_t abase = sb + (uint32_t)buf * A_BYTES +
                               (uint32_t)((wm * 32 + lr) * (A_LDH * 2) + lc * 16);
        // B base: row = lr + kk, col-halves = wn*64 + nc*16 + lc*8
        const uint32_t bbase = sbB + (uint32_t)buf * B_BYTES +
                               (uint32_t)(lr * (B_LDH * 2) + (wn * 64 + lc * 8) * 2);

#pragma unroll
        for (int kk = 0; kk < BK; kk += 16) {
            uint32_t af[2][4];
            ldsm_x4(af[0], abase + kk * 2);
            ldsm_x4(af[1], abase + 16 * (A_LDH * 2) + kk * 2);
#pragma unroll
            for (int nc = 0; nc < 4; nc++) {
                uint32_t bf[4];
                ldsm_x4_t(bf, bbase + kk * (B_LDH * 2) + nc * 32);
                mma_f16(acc[0][2 * nc],     af[0], bf);
                mma_f16(acc[0][2 * nc + 1], af[0], bf + 2);
                mma_f16(acc[1][2 * nc],     af[1], bf);
                mma_f16(acc[1][2 * nc + 1], af[1], bf + 2);
            }
        }
        __syncthreads();
    }

    // ---- epilogue: direct v2 stores ----
    const int crow = m0 + wm * 32 + (lane >> 2);
    const int ccol = n0 + wn * 64 + (lane & 3) * 2;
#pragma unroll
    for (int mt = 0; mt < 2; mt++)
#pragma unroll
        for (int nt = 0; nt < 8; nt++) {
            float* p0 = C + (size_t)(crow + mt * 16) * ldn + ccol + nt * 8;
            float* p1 = p0 + 8 * ldn;
            *reinterpret_cast<float2*>(p0) = make_float2(acc[mt][nt][0], acc[mt][nt][1]);
            *reinterpret_cast<float2*>(p1) = make_float2(acc[mt][nt][2], acc[mt][nt][3]);
        }
}

// ---------------- fused butterfly + gates + modReLU -----------------------
__global__ __launch_bounds__(256) void fuse_kernel(
    const float* __restrict__ state,
    const float* __restrict__ br, const float* __restrict__ bg,
    const float* __restrict__ bc, float* __restrict__ out)
{
    __shared__ float h[DOUT];
    const int row = blockIdx.x;
    const int t = threadIdx.x;
    const float* st = state + (size_t)row * DOUT;

    for (int j = t; j < DOUT; j += 256) h[j] = st[j];
    __syncthreads();

#pragma unroll
    for (int i = 0; i < NCAP; i++) {
        const int hb = 9 - i;
        const int stride = 1 << hb;
#pragma unroll
        for (int pp = 0; pp < 2; pp++) {
            int p = t + pp * 256;
            int m = ((p >> hb) << (hb + 1)) | (p & (stride - 1));
            int q = m & ((1 << (10 - i)) - 1);
            int b = m >> (10 - i);
            int a = (q << i) + b;
            float c = g_cos[i * 512 + a];
            float s = g_sin[i * 512 + a];
            float h0 = h[m], h1 = h[m + stride];
            h[m]          = c * h0 - s * h1;
            h[m + stride] = s * h0 + c * h1;
        }
        __syncthreads();
    }

    const float* uxr = g_Ux + (size_t)row * 3072;
    const float* srr = g_SR + (size_t)row * DOUT;
    const float* sgr = g_SG + (size_t)row * DOUT;

    for (int j = t; j < DOUT; j += 256) {
        float ucx = uxr[j];
        float rv = 1.0f / (1.0f + expf(-(uxr[1024 + j] + srr[j] + br[j])));
        float gv = 1.0f / (1.0f + expf(-(uxr[2048 + j] + sgr[j] + bg[j])));
        float pre = rv * h[j] + ucx;
        float mag = fabsf(pre) + 0.001f + bc[j];
        float sgn = (pre > 0.0f) ? 1.0f : ((pre < 0.0f) ? -1.0f : 0.0f);
        float cv = sgn * fmaxf(mag, 0.0f);
        out[(size_t)row * DOUT + j] = gv * st[j] + (1.0f - gv) * cv;
    }
}

// ---------------- launch ---------------------------------------------------
extern "C" void kernel_launch(void* const* d_in, const int* in_sizes, int n_in,
                              void* d_out, int out_size)
{
    const float* x     = (const float*)d_in[0];
    const float* state = (const float*)d_in[1];
    const float* theta = (const float*)d_in[2];
    const float* U     = (const float*)d_in[3];
    const float* W_r   = (const float*)d_in[4];
    const float* W_g   = (const float*)d_in[5];
    const float* br    = (const float*)d_in[6];
    const float* bg    = (const float*)d_in[7];
    const float* bc    = (const float*)d_in[8];
    float* out = (float*)d_out;

    __half *xh, *sh, *uh, *wrh, *wgh;
    cudaGetSymbolAddress((void**)&xh,  g_xh);
    cudaGetSymbolAddress((void**)&sh,  g_sh);
    cudaGetSymbolAddress((void**)&uh,  g_Uh);
    cudaGetSymbolAddress((void**)&wrh, g_Wrh);
    cudaGetSymbolAddress((void**)&wgh, g_Wgh);

    static bool attr_done = false;
    if (!attr_done) {
        cudaFuncSetAttribute(gemm_mma, cudaFuncAttributeMaxDynamicSharedMemorySize, SMEM_SZ);
        attr_done = true;
    }

    trig_kernel<<<NCAP, 512>>>(theta);
    f2h_kernel<<<1024, 256>>>(x,     xh,  NROWS * 1024 / 4);
    f2h_kernel<<<1024, 256>>>(state, sh,  NROWS * 1024 / 4);
    f2h_kernel<<<1024, 256>>>(U,     uh,  1024 * 3072 / 4);
    f2h_kernel<<<512,  256>>>(W_r,   wrh, 1024 * 1024 / 4);
    f2h_kernel<<<512,  256>>>(W_g,   wgh, 1024 * 1024 / 4);
    gemm_mma<<<1280, 512, SMEM_SZ>>>(xh, sh);
    fuse_kernel<<<NROWS, 256>>>(state, br, bg, bc, out);
}

// round 10
// speedup vs baseline: 3.6237x; 1.0142x over previous
#include <cuda_runtime.h>
#include <cuda_fp16.h>
#include <cstdint>

#define DOUT 1024
#define NROWS 8192
#define NCAP 10
#define KDIM 1024

// ---------------- scratch (device globals: allocation-rule-safe) ----------
__device__ float g_cos[NCAP * 512];
__device__ float g_sin[NCAP * 512];
__device__ float g_Ux[(size_t)NROWS * 3072];
__device__ float g_SR[(size_t)NROWS * 1024];
__device__ float g_SG[(size_t)NROWS * 1024];
__device__ __half g_xh[(size_t)NROWS * 1024];
__device__ __half g_sh[(size_t)NROWS * 1024];
__device__ __half g_Uh[(size_t)1024 * 3072];
__device__ __half g_Wrh[(size_t)1024 * 1024];
__device__ __half g_Wgh[(size_t)1024 * 1024];

// ---------------- helpers ---------------------------------------------------
__device__ __forceinline__ uint32_t smem_u32(const void* p) {
    uint32_t a;
    asm("{ .reg .u64 t; cvta.to.shared.u64 t, %1; cvt.u32.u64 %0, t; }" : "=r"(a) : "l"(p));
    return a;
}
__device__ __forceinline__ void cp16(uint32_t s, const void* g) {
    asm volatile("cp.async.cg.shared.global [%0], [%1], 16;" :: "r"(s), "l"(g));
}
#define CP_COMMIT() asm volatile("cp.async.commit_group;" ::: "memory")
#define CP_WAIT(n)  asm volatile("cp.async.wait_group %0;" :: "n"(n) : "memory")

__device__ __forceinline__ void ldsm_x4(uint32_t* r, uint32_t addr) {
    asm volatile("ldmatrix.sync.aligned.m8n8.x4.shared.b16 {%0,%1,%2,%3}, [%4];"
                 : "=r"(r[0]), "=r"(r[1]), "=r"(r[2]), "=r"(r[3]) : "r"(addr));
}
__device__ __forceinline__ void ldsm_x4_t(uint32_t* r, uint32_t addr) {
    asm volatile("ldmatrix.sync.aligned.m8n8.x4.trans.shared.b16 {%0,%1,%2,%3}, [%4];"
                 : "=r"(r[0]), "=r"(r[1]), "=r"(r[2]), "=r"(r[3]) : "r"(addr));
}
__device__ __forceinline__ void mma_f16(float* d, const uint32_t* a, const uint32_t* b) {
    asm volatile(
        "mma.sync.aligned.m16n8k16.row.col.f32.f16.f16.f32 "
        "{%0,%1,%2,%3}, {%4,%5,%6,%7}, {%8,%9}, {%0,%1,%2,%3};"
        : "+f"(d[0]), "+f"(d[1]), "+f"(d[2]), "+f"(d[3])
        : "r"(a[0]), "r"(a[1]), "r"(a[2]), "r"(a[3]), "r"(b[0]), "r"(b[1]));
}

// ---------------- trig table ----------------------------------------------
__global__ void trig_kernel(const float* __restrict__ theta) {
    int i = blockIdx.x, a = threadIdx.x;
    float s, c;
    sincosf(theta[i * 512 + a], &s, &c);
    g_cos[i * 512 + a] = c;
    g_sin[i * 512 + a] = s;
}

// ---------------- fp32 -> fp16 convert (all 5 arrays, one launch) ----------
__global__ __launch_bounds__(256) void f2h_all(const float* __restrict__ x,
                                               const float* __restrict__ state,
                                               const float* __restrict__ U,
                                               const float* __restrict__ Wr,
                                               const float* __restrict__ Wg) {
    const float* in; __half* out; int n4;
    switch (blockIdx.y) {
        case 0: in = x;     out = g_xh;  n4 = NROWS * 1024 / 4; break;
        case 1: in = state; out = g_sh;  n4 = NROWS * 1024 / 4; break;
        case 2: in = U;     out = g_Uh;  n4 = 1024 * 3072 / 4;  break;
        case 3: in = Wr;    out = g_Wrh; n4 = 1024 * 1024 / 4;  break;
        default: in = Wg;   out = g_Wgh; n4 = 1024 * 1024 / 4;  break;
    }
    int i = blockIdx.x * 256 + threadIdx.x;
    int stride = gridDim.x * 256;
    for (; i < n4; i += stride) {
        float4 v = reinterpret_cast<const float4*>(in)[i];
        __half2 h0 = __floats2half2_rn(v.x, v.y);
        __half2 h1 = __floats2half2_rn(v.z, v.w);
        uint2 u;
        u.x = *reinterpret_cast<const uint32_t*>(&h0);
        u.y = *reinterpret_cast<const uint32_t*>(&h1);
        reinterpret_cast<uint2*>(out)[i] = u;
    }
}

// ---------------- mma.sync fp16 GEMM ---------------------------------------
// C[M,N] = A[M,K] * B[K,N] (fp16 in, fp32 acc). BM=128, BN=256, BK=32.
// 256 threads = 8 warps (2 along M x 4 along N), warp tile 64x64.
constexpr int BM = 128, BN = 256, BK = 32, S = 4;
constexpr int NSTAGE = KDIM / BK;            // 32
constexpr int A_LDH = 40;                    // halves per A row
constexpr int B_LDH = 264;                   // halves per B row
constexpr int A_BYTES = BM * A_LDH * 2;      // 10240
constexpr int B_BYTES = BK * B_LDH * 2;      // 16896
constexpr int B_BASE = S * A_BYTES;          // 40960
constexpr int SMEM_SZ = B_BASE + S * B_BYTES; // 108544 B

__global__ __launch_bounds__(256, 1) void gemm_mma(const __half* __restrict__ xh,
                                                   const __half* __restrict__ sh) {
    extern __shared__ __align__(1024) char smem[];
    const uint32_t sb = smem_u32(smem);
    const uint32_t sbB = sb + B_BASE;

    const int tid  = threadIdx.x;
    const int lane = tid & 31;
    const int wid  = tid >> 5;
    const int wm   = wid >> 2;   // 0..1 (64 rows each)
    const int wn   = wid & 3;    // 0..3 (64 cols each)

    // ---- tile mapping: 768 U-tiles, then 256 Wr, 256 Wg ----
    const __half* A; const __half* B; float* C; int ldn, m0, n0;
    int bid = blockIdx.x;
    if (bid < 768) {
        A = xh; B = g_Uh; C = g_Ux; ldn = 3072;
        m0 = (bid & 63) * BM; n0 = (bid >> 6) * BN;
    } else {
        int t = bid - 768, g = t >> 8, tt = t & 255;
        A = sh; B = g ? g_Wgh : g_Wrh; C = g ? g_SG : g_SR; ldn = 1024;
        m0 = (tt & 63) * BM; n0 = (tt >> 6) * BN;
    }

    // ---- stage loader (256 threads) ----
    auto load_stage = [&](int st) {
        const int buf = st & (S - 1);
        const __half* Ag = A + (size_t)m0 * KDIM + st * BK;
        const uint32_t ab = sb + (uint32_t)(buf * A_BYTES);
#pragma unroll
        for (int i = 0; i < 2; i++) {   // A: 512 chunks of 16B
            int idx = tid + i * 256;
            int r = idx >> 2, c = idx & 3;
            cp16(ab + (uint32_t)(r * (A_LDH * 2) + c * 16),
                 Ag + (size_t)r * KDIM + c * 8);
        }
        const __half* Bg = B + (size_t)st * BK * ldn + n0;
        const uint32_t bb = sbB + (uint32_t)(buf * B_BYTES);
#pragma unroll
        for (int i = 0; i < 4; i++) {   // B: 1024 chunks of 16B
            int idx = tid + i * 256;
            int k = idx >> 5, c = idx & 31;
            cp16(bb + (uint32_t)(k * (B_LDH * 2) + c * 16),
                 Bg + (size_t)k * ldn + c * 8);
        }
        CP_COMMIT();
    };

    load_stage(0);
    load_stage(1);
    load_stage(2);

    float acc[4][8][4];
#pragma unroll
    for (int mt = 0; mt < 4; mt++)
#pragma unroll
        for (int nt = 0; nt < 8; nt++)
#pragma unroll
            for (int j = 0; j < 4; j++) acc[mt][nt][j] = 0.0f;

    const int lr = lane & 15;      // ldmatrix row provider
    const int lc = lane >> 4;      // ldmatrix col-chunk provider

    for (int ks = 0; ks < NSTAGE; ks++) {
        CP_WAIT(2);
        __syncthreads();
        if (ks + 3 < NSTAGE) load_stage(ks + 3); else CP_COMMIT();

        const int buf = ks & (S - 1);
        const uint32_t abase = sb + (uint32_t)buf * A_BYTES +
                               (uint32_t)((wm * 64 + lr) * (A_LDH * 2) + lc * 16);
        const uint32_t bbase = sbB + (uint32_t)buf * B_BYTES +
                               (uint32_t)(lr * (B_LDH * 2) + (wn * 64 + lc * 8) * 2);

#pragma unroll
        for (int kk = 0; kk < BK; kk += 16) {
            uint32_t af[4][4];
#pragma unroll
            for (int mt = 0; mt < 4; mt++)
                ldsm_x4(af[mt], abase + mt * 16 * (A_LDH * 2) + kk * 2);
            uint32_t bf[4][4];
#pragma unroll
            for (int nc = 0; nc < 4; nc++)
                ldsm_x4_t(bf[nc], bbase + kk * (B_LDH * 2) + nc * 32);
#pragma unroll
            for (int mt = 0; mt < 4; mt++)
#pragma unroll
                for (int nc = 0; nc < 4; nc++) {
                    mma_f16(acc[mt][2 * nc],     af[mt], bf[nc]);
                    mma_f16(acc[mt][2 * nc + 1], af[mt], bf[nc] + 2);
                }
        }
        __syncthreads();
    }

    // ---- epilogue: direct v2 stores ----
    const int crow = m0 + wm * 64 + (lane >> 2);
    const int ccol = n0 + wn * 64 + (lane & 3) * 2;
#pragma unroll
    for (int mt = 0; mt < 4; mt++)
#pragma unroll
        for (int nt = 0; nt < 8; nt++) {
            float* p0 = C + (size_t)(crow + mt * 16) * ldn + ccol + nt * 8;
            float* p1 = p0 + 8 * ldn;
            *reinterpret_cast<float2*>(p0) = make_float2(acc[mt][nt][0], acc[mt][nt][1]);
            *reinterpret_cast<float2*>(p1) = make_float2(acc[mt][nt][2], acc[mt][nt][3]);
        }
}

// ---------------- fused butterfly + gates + modReLU -----------------------
__global__ __launch_bounds__(256) void fuse_kernel(
    const float* __restrict__ state,
    const float* __restrict__ br, const float* __restrict__ bg,
    const float* __restrict__ bc, float* __restrict__ out)
{
    __shared__ float h[DOUT];
    const int row = blockIdx.x;
    const int t = threadIdx.x;
    const float* st = state + (size_t)row * DOUT;

    for (int j = t; j < DOUT; j += 256) h[j] = st[j];
    __syncthreads();

#pragma unroll
    for (int i = 0; i < NCAP; i++) {
        const int hb = 9 - i;
        const int stride = 1 << hb;
#pragma unroll
        for (int pp = 0; pp < 2; pp++) {
            int p = t + pp * 256;
            int m = ((p >> hb) << (hb + 1)) | (p & (stride - 1));
            int q = m & ((1 << (10 - i)) - 1);
            int b = m >> (10 - i);
            int a = (q << i) + b;
            float c = g_cos[i * 512 + a];
            float s = g_sin[i * 512 + a];
            float h0 = h[m], h1 = h[m + stride];
            h[m]          = c * h0 - s * h1;
            h[m + stride] = s * h0 + c * h1;
        }
        __syncthreads();
    }

    const float* uxr = g_Ux + (size_t)row * 3072;
    const float* srr = g_SR + (size_t)row * DOUT;
    const float* sgr = g_SG + (size_t)row * DOUT;

    for (int j = t; j < DOUT; j += 256) {
        float ucx = uxr[j];
        float rv = 1.0f / (1.0f + expf(-(uxr[1024 + j] + srr[j] + br[j])));
        float gv = 1.0f / (1.0f + expf(-(uxr[2048 + j] + sgr[j] + bg[j])));
        float pre = rv * h[j] + ucx;
        float mag = fabsf(pre) + 0.001f + bc[j];
        float sgn = (pre > 0.0f) ? 1.0f : ((pre < 0.0f) ? -1.0f : 0.0f);
        float cv = sgn * fmaxf(mag, 0.0f);
        out[(size_t)row * DOUT + j] = gv * st[j] + (1.0f - gv) * cv;
    }
}

// ---------------- launch ---------------------------------------------------
extern "C" void kernel_launch(void* const* d_in, const int* in_sizes, int n_in,
                              void* d_out, int out_size)
{
    const float* x     = (const float*)d_in[0];
    const float* state = (const float*)d_in[1];
    const float* theta = (const float*)d_in[2];
    const float* U     = (const float*)d_in[3];
    const float* W_r   = (const float*)d_in[4];
    const float* W_g   = (const float*)d_in[5];
    const float* br    = (const float*)d_in[6];
    const float* bg    = (const float*)d_in[7];
    const float* bc    = (const float*)d_in[8];
    float* out = (float*)d_out;

    __half *xh, *sh;
    cudaGetSymbolAddress((void**)&xh, g_xh);
    cudaGetSymbolAddress((void**)&sh, g_sh);

    static bool attr_done = false;
    if (!attr_done) {
        cudaFuncSetAttribute(gemm_mma, cudaFuncAttributeMaxDynamicSharedMemorySize, SMEM_SZ);
        attr_done = true;
    }

    trig_kernel<<<NCAP, 512>>>(theta);
    f2h_all<<<dim3(384, 5), 256>>>(x, state, U, W_r, W_g);
    gemm_mma<<<1280, 256, SMEM_SZ>>>(xh, sh);
    fuse_kernel<<<NROWS, 256>>>(state, br, bg, bc, out);
}